// round 11
// baseline (speedup 1.0000x reference)
#include <cuda_runtime.h>
#include <cuda_fp16.h>
#include <mma.h>
#include <cstdint>
using namespace nvcuda;

#define NN 16384
#define NE 8192
#define CH 256
#define S20 1048576.0f   // 2^20 exact

// ------------- device-global scratch (allocation-free) -------------
__device__ __align__(256) __half g_B1h[(size_t)NN * NE];  // 256 MB fp16 incidence
__device__ __align__(256) __half g_x0h[NN * CH];
__device__ __align__(256) __half g_W0h[CH * CH];
__device__ __align__(256) __half g_W1h[CH * CH];
__device__ __align__(256) __half g_Yh [NN * CH];          // nc[n] * (x0@W0)
__device__ __align__(256) __half g_X1h[NE * CH];          // x_1 (pre-relu)
__device__ __align__(256) __half g_X1Wh[NE * CH];         // ec*S * (x1@W1)
__device__ __align__(256) float  g_acc[NN * CH];          // raw GEMM accum (reused)
__device__ float g_rowsum[NN], g_colsum[NE], g_d1s[NE];
__device__ float g_nc[NN], g_ec[NE], g_ecS[NE], g_d0invS[NN];

__device__ __forceinline__ void cp16(uint32_t d, const void* s) {
    asm volatile("cp.async.cg.shared.global [%0],[%1],16;" :: "r"(d), "l"(s));
}

// ------------- prep kernels -------------
__global__ void k_zero() {
    int t = blockIdx.x * 256 + threadIdx.x;
    if (t < NN) g_rowsum[t] = 0.f;
    if (t < NE) { g_colsum[t] = 0.f; g_d1s[t] = 0.f; }
}

// Convert B1 f32->fp16 + row/col sums. grid (NE/256, NN/64), 256 thr.
__global__ void __launch_bounds__(256) k_conv(const float* __restrict__ B1) {
    __shared__ float srow[64];
    const int t = threadIdx.x;
    const int e = blockIdx.x * 256 + t;
    const int n0 = blockIdx.y * 64;
    if (t < 64) srow[t] = 0.f;
    __syncthreads();
    float ca = 0.f;
    for (int i = 0; i < 64; ++i) {
        size_t gi = (size_t)(n0 + i) * NE + e;
        float v = B1[gi];
        g_B1h[gi] = __float2half_rn(v);
        ca += v;
        float w = v;
        #pragma unroll
        for (int o = 16; o; o >>= 1) w += __shfl_xor_sync(0xffffffffu, w, o);
        if ((t & 31) == 0) atomicAdd(&srow[i], w);
    }
    atomicAdd(&g_colsum[e], ca);
    __syncthreads();
    if (t < 64) atomicAdd(&g_rowsum[n0 + t], srow[t]);
}

__global__ void k_card() {
    int t = blockIdx.x * 256 + threadIdx.x;
    if (t < NN) g_nc[t] = rsqrtf(g_rowsum[t]);            // card^-0.5
    if (t < NE) {
        float r = rsqrtf(g_colsum[t]);
        float e = r * r * r;                               // card^-1.5
        g_ec[t] = e; g_ecS[t] = e * S20;
    }
}

// d0invS[n] = 1 / (S * sum_e B1[n,e]*ec[e]).  grid NN, 256 thr.
__global__ void __launch_bounds__(256) k_d0() {
    const int n = blockIdx.x, t = threadIdx.x;
    const __half2* row = (const __half2*)&g_B1h[(size_t)n * NE];
    float s = 0.f;
    for (int j = t; j < NE / 2; j += 256) {
        float2 f = __half22float2(row[j]);
        s += f.x * g_ec[2 * j] + f.y * g_ec[2 * j + 1];
    }
    #pragma unroll
    for (int o = 16; o; o >>= 1) s += __shfl_xor_sync(0xffffffffu, s, o);
    __shared__ float red[8];
    if ((t & 31) == 0) red[t >> 5] = s;
    __syncthreads();
    if (t == 0) {
        float tot = 0.f;
        #pragma unroll
        for (int w = 0; w < 8; ++w) tot += red[w];
        g_d0invS[n] = 1.f / (S20 * tot);
    }
}

// d1s[e] += sum_n B1[n,e]*nc[n].  grid (NE/256, NN/256).
__global__ void __launch_bounds__(256) k_d1() {
    const int e = blockIdx.x * 256 + threadIdx.x;
    const int n0 = blockIdx.y * 256;
    float s = 0.f;
    for (int i = 0; i < 256; ++i)
        s += __half2float(g_B1h[(size_t)(n0 + i) * NE + e]) * g_nc[n0 + i];
    atomicAdd(&g_d1s[e], s);
}

__global__ void k_cvt(const float* __restrict__ x0, const float* __restrict__ W0,
                      const float* __restrict__ W1) {
    int t = blockIdx.x * 256 + threadIdx.x;
    g_x0h[t] = __float2half_rn(x0[t]);
    if (t < CH * CH) {
        g_W0h[t] = __float2half_rn(W0[t]);
        g_W1h[t] = __float2half_rn(W1[t]);
    }
}

// ------------- unified GEMM: acc(Mx256) = A(MxK) @ B(Kx256) -------------
// EPI0: A=x0h  (rm,K=CH), B=W0h   | EPI1: A=B1^T (cm from B1h, K=NN), B=Yh
// EPI2: A=X1h  (rm,K=CH), B=W1h   | EPI3: A=B1h  (rm,K=NE),          B=X1Wh
template <int EPI>
__global__ void __launch_bounds__(256) k_gemm() {
    constexpr int K   = (EPI == 0) ? CH : (EPI == 1) ? NN : (EPI == 2) ? CH : NE;
    constexpr bool TR = (EPI == 1);
    constexpr int LDA = (EPI == 0 || EPI == 2) ? CH : NE;
    const __half* A = (EPI == 0) ? g_x0h : (EPI == 2) ? g_X1h : g_B1h;
    const __half* B = (EPI == 0) ? g_W0h : (EPI == 1) ? g_Yh
                    : (EPI == 2) ? g_W1h : g_X1Wh;

    __shared__ __align__(32) __half As[2][2560];      // rm: [m][k] pitch40 ; cm: [k][m] pitch72
    __shared__ __align__(32) __half Bs[2][32 * 264];  // [k][n] pitch 264

    const int t = threadIdx.x;
    const int m0 = blockIdx.x * 64;
    const uint32_t asb = (uint32_t)__cvta_generic_to_shared(&As[0][0]);
    const uint32_t bsb = (uint32_t)__cvta_generic_to_shared(&Bs[0][0]);

    wmma::fragment<wmma::accumulator, 16, 16, 16, float> acc[2][4];
    #pragma unroll
    for (int i = 0; i < 2; ++i)
        #pragma unroll
        for (int j = 0; j < 4; ++j) wmma::fill_fragment(acc[i][j], 0.f);

    auto load = [&](int s, int k0) {
        if (TR) {
            int k = t >> 3, mc = (t & 7) * 8;
            cp16(asb + (uint32_t)(s * 2560 + k * 72 + mc) * 2,
                 A + (size_t)(k0 + k) * LDA + m0 + mc);
        } else {
            int m = t >> 2, kc = (t & 3) * 8;
            cp16(asb + (uint32_t)(s * 2560 + m * 40 + kc) * 2,
                 A + (size_t)(m0 + m) * LDA + k0 + kc);
        }
        #pragma unroll
        for (int j = 0; j < 4; ++j) {
            int lin = j * 256 + t;
            int k = lin >> 5, nc = (lin & 31) * 8;
            cp16(bsb + (uint32_t)(s * 32 * 264 + k * 264 + nc) * 2,
                 B + (size_t)(k0 + k) * CH + nc);
        }
    };

    constexpr int KT = K / 32;
    load(0, 0);
    asm volatile("cp.async.commit_group;");

    const int wid = t >> 5, wm = wid >> 2, wn = wid & 3;

    for (int kt = 0; kt < KT; ++kt) {
        const int s = kt & 1;
        if (kt + 1 < KT) load(s ^ 1, (kt + 1) * 32);
        asm volatile("cp.async.commit_group;");
        asm volatile("cp.async.wait_group 1;");
        __syncthreads();
        #pragma unroll
        for (int ks = 0; ks < 2; ++ks) {
            wmma::fragment<wmma::matrix_b, 16, 16, 16, __half, wmma::row_major> bf[4];
            #pragma unroll
            for (int nb = 0; nb < 4; ++nb)
                wmma::load_matrix_sync(bf[nb], &Bs[s][(ks * 16) * 264 + wn * 64 + nb * 16], 264);
            if (TR) {
                wmma::fragment<wmma::matrix_a, 16, 16, 16, __half, wmma::col_major> af[2];
                #pragma unroll
                for (int ma = 0; ma < 2; ++ma)
                    wmma::load_matrix_sync(af[ma], &As[s][(ks * 16) * 72 + wm * 32 + ma * 16], 72);
                #pragma unroll
                for (int ma = 0; ma < 2; ++ma)
                    #pragma unroll
                    for (int nb = 0; nb < 4; ++nb)
                        wmma::mma_sync(acc[ma][nb], af[ma], bf[nb], acc[ma][nb]);
            } else {
                wmma::fragment<wmma::matrix_a, 16, 16, 16, __half, wmma::row_major> af[2];
                #pragma unroll
                for (int ma = 0; ma < 2; ++ma)
                    wmma::load_matrix_sync(af[ma], &As[s][(wm * 32 + ma * 16) * 40 + ks * 16], 40);
                #pragma unroll
                for (int ma = 0; ma < 2; ++ma)
                    #pragma unroll
                    for (int nb = 0; nb < 4; ++nb)
                        wmma::mma_sync(acc[ma][nb], af[ma], bf[nb], acc[ma][nb]);
            }
        }
        __syncthreads();
    }
    #pragma unroll
    for (int ma = 0; ma < 2; ++ma)
        #pragma unroll
        for (int nb = 0; nb < 4; ++nb)
            wmma::store_matrix_sync(&g_acc[(size_t)(m0 + wm * 32 + ma * 16) * CH + wn * 64 + nb * 16],
                                    acc[ma][nb], CH, wmma::mem_row_major);
}

// ------------- epilogues -------------
template <int EPI>
__global__ void k_epi(const float* __restrict__ bias, float* __restrict__ outF) {
    int t = blockIdx.x * 256 + threadIdx.x;
    int row = t >> 8, col = t & 255;
    float a = g_acc[t];
    if (EPI == 0) g_Yh[t] = __float2half_rn(a * g_nc[row]);
    if (EPI == 1) {
        float v = a / g_d1s[row] + bias[col];
        g_X1h[t] = __float2half_rn(v);
        if (outF) outF[t] = fmaxf(v, 0.f);
    }
    if (EPI == 2) g_X1Wh[t] = __float2half_rn(a * g_ecS[row]);
    if (EPI == 3) outF[t] = fmaxf(a * g_d0invS[row] + bias[col], 0.f);
}

// ------------- launch -------------
extern "C" void kernel_launch(void* const* d_in, const int* in_sizes, int n_in,
                              void* d_out, int out_size) {
    const float* x0  = (const float*)d_in[0];
    const float* B1  = (const float*)d_in[1];
    const float* W0  = (const float*)d_in[2];
    const float* W1  = (const float*)d_in[3];
    const float* b01 = (const float*)d_in[4];
    const float* b10 = (const float*)d_in[5];
    float* out = (float*)d_out;
    float* out_x1 = (out_size >= NN * CH + NE * CH) ? out + (size_t)NN * CH : nullptr;

    k_zero<<<64, 256>>>();
    k_conv<<<dim3(NE / 256, NN / 64), 256>>>(B1);
    k_cvt <<<NN * CH / 256, 256>>>(x0, W0, W1);
    k_card<<<NN / 256, 256>>>();
    k_d0  <<<NN, 256>>>();
    k_d1  <<<dim3(NE / 256, NN / 256), 256>>>();

    k_gemm<0><<<NN / 64, 256>>>();
    k_epi <0><<<NN * CH / 256, 256>>>(nullptr, nullptr);
    k_gemm<1><<<NE / 64, 256>>>();
    k_epi <1><<<NE * CH / 256, 256>>>(b01, out_x1);
    k_gemm<2><<<NE / 64, 256>>>();
    k_epi <2><<<NE * CH / 256, 256>>>(nullptr, nullptr);
    k_gemm<3><<<NN / 64, 256>>>();
    k_epi <3><<<NN * CH / 256, 256>>>(b10, out);
}